// round 16
// baseline (speedup 1.0000x reference)
#include <cuda_runtime.h>
#include <cstdint>
#include <cstring>

// ============================================================================
// Sparse masked CNN pyramid (14 levels) + MLP head — round 16.
// = R13 (286.8us) + tap-identity bucketing of L1/L2 position lists:
//   phase0 passA counts 10 buckets (single-tap d=0..8, multi=9);
//   grid barrier; passB scatters g_pos -> g_pos2 and rewrites g_idx;
//   convk uses a warp-uniform mask-driven tap loop (executes only active taps).
// ============================================================================

#define CAP 131072
#define NLEV 14
#define IDX_TOTAL 5592407

__device__ __align__(16) float g_FA[CAP * 32];
__device__ __align__(16) float g_FB[CAP * 32];
__device__ int   g_idx[IDX_TOTAL];
__device__ int   g_pos[NLEV * CAP];
__device__ int   g_pos2[2 * CAP];          // sorted L1 / L2 position lists
__device__ int   g_cnt[NLEV];              // zero-init; block0 re-zeroes at end
__device__ int   g_scnt[40];               // bucket counts[20] + cursors[20]
__device__ float g_pools[NLEV * 32];       // zero-init; block0 re-zeroes at end
__device__ volatile unsigned g_bars[16];   // zeroed by build_all0 each replay

__constant__ int c_LS[NLEV]   = {2048,1024,512,256,128,64,32,16,8,4,2,1,1,1};
__constant__ int c_IOFS[NLEV] = {0,4194304,5242880,5505024,5570560,5586944,5591040,
                                 5592064,5592320,5592384,5592400,5592404,5592405,5592406};

#define FMA2(d, a, b, c) \
    asm("fma.rn.f32x2 %0, %1, %2, %3;" : "=l"(d) : "l"(a), "l"(b), "l"(c))
#define ADD2(d, a, b) \
    asm("add.rn.f32x2 %0, %1, %2;" : "=l"(d) : "l"(a), "l"(b))
#define PACK_DUP(d, a) \
    do { unsigned _u = __float_as_uint(a); \
         asm("mov.b64 %0, {%1, %1};" : "=l"(d) : "r"(_u)); } while (0)

__device__ __forceinline__ float2 upk(unsigned long long a) {
    float2 f; memcpy(&f, &a, 8); return f;
}

// ---- grid-wide barriers (per-epoch counters, reset by next build_all0) -------
__device__ __forceinline__ void gwait(int e, unsigned nb) {
    __syncthreads();
    if (threadIdx.x == 0) {
        __threadfence();
        atomicAdd((unsigned*)&g_bars[e], 1u);
        while (g_bars[e] < nb) __nanosleep(128);
        __threadfence();
    }
    __syncthreads();
}
__device__ __forceinline__ void garrive(int e) {
    __syncthreads();
    __threadfence();
    if (threadIdx.x == 0) atomicAdd((unsigned*)&g_bars[e], 1u);
}

// ---- 9-tap activity key: 0..8 = single active tap d, 9 = multiple ------------
__device__ __forceinline__ int tapkey(int pw, const int* __restrict__ Ip, int sp) {
    int pi = pw >> 16, pj = pw & 0xffff;
    unsigned m = 0;
    #pragma unroll
    for (int d = 0; d < 9; d++) {
        int r = 2 * pi + d / 3 - 1;
        int c = 2 * pj + d % 3 - 1;
        if ((unsigned)r < (unsigned)sp && (unsigned)c < (unsigned)sp)
            if (Ip[r * sp + c] >= 0) m |= 1u << d;
    }
    return (__popc(m) == 1) ? (__ffs(m) - 1) : 9;
}

// ---- block compaction step (1024-thread blocks only) -------------------------
__device__ __forceinline__ void emit(int level, bool act, int lin, int posword,
                                     int iofs, unsigned* bitdst) {
    __shared__ int ewcnt[32];
    __shared__ int ewbase[32];
    __shared__ int ebbase;
    int tid = threadIdx.x, wid = tid >> 5, lane = tid & 31;
    unsigned m = __ballot_sync(0xffffffffu, act);
    if (lane == 0) {
        ewcnt[wid] = __popc(m);
        if (bitdst) bitdst[wid] = m;
    }
    __syncthreads();
    if (tid < 32) {
        int cc = ewcnt[tid];
        int x = cc;
        #pragma unroll
        for (int o = 1; o < 32; o <<= 1) {
            int y = __shfl_up_sync(0xffffffffu, x, o);
            if (tid >= o) x += y;
        }
        ewbase[tid] = x - cc;
        if (tid == 31) ebbase = atomicAdd(&g_cnt[level], x);
    }
    __syncthreads();
    int idx = -1;
    if (act) {
        idx = ebbase + ewbase[wid] + __popc(m & ((1u << lane) - 1u));
        if (idx < CAP) g_pos[level * CAP + idx] = posword;
        else idx = -1;
    }
    if (lin >= 0) g_idx[iofs + lin] = idx;
    __syncthreads();
}

__device__ __forceinline__ int getbit(const unsigned* a, int c) {
    return (a[c >> 5] >> (c & 31)) & 1;
}

// ---- build: levels 0..7; zero barrier + sort counters -------------------------
__global__ __launch_bounds__(1024) void build_all0(const float* __restrict__ mask) {
    if (blockIdx.x == 0) {
        if (threadIdx.x < 16) g_bars[threadIdx.x] = 0;
        else if (threadIdx.x < 56) g_scnt[threadIdx.x - 16] = 0;
    }

    __shared__ unsigned a0[512];
    __shared__ unsigned a1[128];
    __shared__ unsigned a2[32];
    __shared__ unsigned a3[8];
    __shared__ unsigned a4[32];
    __shared__ unsigned a5[32];
    __shared__ unsigned a6[32];
    int tid = threadIdx.x;
    int tx = blockIdx.x & 15, ty = blockIdx.x >> 4;

    for (int r = 0; r < 16; r++) {
        int c = r * 1024 + tid;
        int li = c >> 7, lj = c & 127;
        int i = ty * 128 + li, j = tx * 128 + lj;
        bool act = (mask[i * 2048 + j] != 0.0f);
        emit(0, act, i * 2048 + j, (i << 16) | j, c_IOFS[0], a0 + r * 32);
    }
    unsigned* bits[8] = {a0, a1, a2, a3, a4, a5, a6, nullptr};
    #pragma unroll
    for (int L = 1; L <= 7; L++) {
        int t = 128 >> L;
        int cells = t * t;
        int chunks = (cells + 1023) >> 10;
        int tprev = t * 2;
        for (int r = 0; r < chunks; r++) {
            int c = r * 1024 + tid;
            bool act = false;
            int lin = -1, pw = 0;
            if (c < cells) {
                int li = c / t, lj = c - li * t;
                int c00 = (2 * li) * tprev + 2 * lj;
                const unsigned* pb = bits[L - 1];
                act = getbit(pb, c00) | getbit(pb, c00 + 1) |
                      getbit(pb, c00 + tprev) | getbit(pb, c00 + tprev + 1);
                int i = ty * t + li, j = tx * t + lj;
                lin = i * (2048 >> L) + j;
                pw = (i << 16) | j;
            }
            emit(L, act, lin, pw, c_IOFS[L], (L < 7) ? (bits[L] + r * 32) : nullptr);
        }
    }
}

// ---- persistent main kernel ---------------------------------------------------
__global__ __launch_bounds__(256, 4) void main_kernel(
    const float* __restrict__ x,  const float* __restrict__ w1,
    const float* __restrict__ ws,
    const float* __restrict__ wm1, const float* __restrict__ bm1,
    const float* __restrict__ wm2, const float* __restrict__ bm2,
    float* __restrict__ out) {
    __shared__ __align__(128) float sW[9216];
    __shared__ float spool[32];
    __shared__ unsigned sball[2];
    int tid = threadIdx.x, bid = blockIdx.x;
    int lane = tid & 31;
    unsigned nb_ = gridDim.x;

    // ================= phase 0: conv1 + build_top (last block) + sort passA ===
    for (int t = tid; t < 800; t += 256) sW[t] = w1[t];
    if (tid < 32) spool[tid] = 0.f;
    __syncthreads();
    {
        int n = min(g_cnt[0], CAP);
        int gw = (bid * 256 + tid) >> 5;
        int nw = (int)nb_ * 8;
        float pl = 0.f;
        for (int p = gw; p < n; p += nw) {
            int pw = g_pos[p];
            int i = pw >> 16, j = pw & 0xffff;
            float acc = 0.f;
            #pragma unroll
            for (int dy = 0; dy < 5; dy++) {
                int r = i + dy - 2;
                bool rv = (unsigned)r < 2048u;
                #pragma unroll
                for (int dx = 0; dx < 5; dx++) {
                    int cc = j + dx - 2;
                    float xv = (rv && (unsigned)cc < 2048u) ? x[r * 2048 + cc] : 0.f;
                    acc = fmaf(xv, sW[(dy * 5 + dx) * 32 + lane], acc);
                }
            }
            acc = fmaxf(acc, 0.f);
            g_FA[(size_t)p * 32 + lane] = acc;
            pl += acc;
        }
        atomicAdd(&spool[lane], pl);
    }
    if (bid == nb_ - 1) {
        for (int k = 8; k < NLEV; k++) {
            int s = c_LS[k], sp = c_LS[k - 1];
            int cells = s * s;
            const int* Ip = g_idx + c_IOFS[k - 1];
            bool act = false;
            int pwv = 0;
            if (tid < cells) {
                int i = tid / s, j = tid - i * s;
                #pragma unroll
                for (int di = 0; di < 2; di++)
                    #pragma unroll
                    for (int dj = 0; dj < 2; dj++) {
                        int r = 2 * i + di, cc = 2 * j + dj;
                        if (r < sp && cc < sp && __ldcg(&Ip[r * sp + cc]) >= 0)
                            act = true;
                    }
                pwv = (i << 16) | j;
            }
            unsigned m = __ballot_sync(0xffffffffu, act);
            if (tid == 0)  sball[0] = m;
            if (tid == 32) sball[1] = m;
            __syncthreads();
            int cnt0 = __popc(sball[0]);
            int total = cnt0 + (cells > 32 ? __popc(sball[1]) : 0);
            if (tid == 0) g_cnt[k] = total;
            if (tid < cells) {
                int idx = -1;
                if (act) {
                    idx = (tid < 32 ? 0 : cnt0) + __popc(m & ((1u << (tid & 31)) - 1u));
                    g_pos[k * CAP + idx] = pwv;
                }
                g_idx[c_IOFS[k] + tid] = idx;
            }
            __syncthreads();
        }
    }
    __syncthreads();
    if (tid < 32) atomicAdd(&g_pools[tid], spool[tid]);

    // ---- sort pass A: count buckets for L1, L2 --------------------------------
    #pragma unroll 1
    for (int L = 1; L <= 2; L++) {
        int n = min(g_cnt[L], CAP);
        int sp = c_LS[L - 1];
        const int* Ip = g_idx + c_IOFS[L - 1];
        const int* posl = g_pos + L * CAP;
        int cbase = (L - 1) * 10;
        for (int p0 = bid * 256; p0 < n; p0 += (int)nb_ * 256) {
            int p = p0 + tid;
            int key = (p < n) ? tapkey(posl[p], Ip, sp) : -1;
            #pragma unroll 1
            for (int k = 0; k < 10; k++) {
                unsigned m = __ballot_sync(0xffffffffu, key == k);
                if (m && key == k && lane == (__ffs(m) - 1))
                    atomicAdd(&g_scnt[cbase + k], __popc(m));
            }
        }
    }
    gwait(0, nb_);

    // ---- sort pass B: scatter into g_pos2 + rewrite g_idx ---------------------
    #pragma unroll 1
    for (int L = 1; L <= 2; L++) {
        int n = min(g_cnt[L], CAP);
        int sp = c_LS[L - 1];
        int sL = c_LS[L];
        const int* Ip = g_idx + c_IOFS[L - 1];
        const int* posl = g_pos + L * CAP;
        int cbase = (L - 1) * 10, obase = 20 + (L - 1) * 10;
        for (int p0 = bid * 256; p0 < n; p0 += (int)nb_ * 256) {
            int p = p0 + tid;
            int pw = (p < n) ? posl[p] : 0;
            int key = (p < n) ? tapkey(pw, Ip, sp) : -1;
            int newp = 0;
            int s = 0;
            #pragma unroll 1
            for (int k = 0; k < 10; k++) {
                int ck = g_scnt[cbase + k];      // final counts (post-barrier)
                unsigned m = __ballot_sync(0xffffffffu, key == k);
                if (m) {
                    int ldr = __ffs(m) - 1;
                    int b = 0;
                    if (lane == ldr && key == k)
                        b = atomicAdd(&g_scnt[obase + k], __popc(m));
                    b = __shfl_sync(0xffffffffu, b, ldr);
                    if (key == k)
                        newp = s + b + __popc(m & ((1u << lane) - 1u));
                }
                s += ck;
            }
            if (key >= 0) {
                g_pos2[(L - 1) * CAP + newp] = pw;
                int pi = pw >> 16, pj = pw & 0xffff;
                g_idx[c_IOFS[L] + pi * sL + pj] = newp;
            }
        }
    }

    // ================= levels 1..7: mask-driven sparse conv ====================
    int pid = tid >> 2;            // 0..63 position within 64-pos step
    int chb = (tid & 3) * 8;       // 8 output channels
    #pragma unroll 1
    for (int L = 1; L <= 7; L++) {
        {   // stage this level's weights + zero spool before the barrier
            const float4* src = (const float4*)(ws + (size_t)(L - 1) * 9216);
            float4* dst = (float4*)sW;
            #pragma unroll
            for (int t = 0; t < 9; t++) dst[tid + t * 256] = src[tid + t * 256];
        }
        if (tid < 32) spool[tid] = 0.f;
        gwait(L, nb_);             // previous phase complete grid-wide

        const float* __restrict__ Fp = (L & 1) ? g_FA : g_FB;
        float* __restrict__ Fc = (L & 1) ? g_FB : g_FA;
        int sp = c_LS[L - 1];
        const int* __restrict__ Ip = g_idx + c_IOFS[L - 1];
        const int* __restrict__ posl =
            (L <= 2) ? (g_pos2 + (size_t)(L - 1) * CAP) : (g_pos + (size_t)L * CAP);
        int n = min(g_cnt[L], CAP);

        int chunk = (n + (int)nb_ - 1) / (int)nb_;
        int start = bid * chunk;
        int pend  = min(start + chunk, n);

        unsigned long long pool[4] = {0ull, 0ull, 0ull, 0ull};
        for (int base = start; base < pend; base += 64) {
            int p = base + pid;
            int pw = (p < pend) ? posl[p] : -1;
            int pi = pw >> 16, pj = pw & 0xffff;

            // 9-bit activity mask (parallel index LDGs; values re-read per tap)
            unsigned actb = 0;
            #pragma unroll
            for (int d = 0; d < 9; d++) {
                if (pw >= 0) {
                    int r = 2 * pi + d / 3 - 1;
                    int c = 2 * pj + d % 3 - 1;
                    if ((unsigned)r < (unsigned)sp && (unsigned)c < (unsigned)sp)
                        if (Ip[r * sp + c] >= 0) actb |= 1u << d;
                }
            }
            unsigned wact = __reduce_or_sync(0xffffffffu, actb);

            unsigned long long acc[4] = {0ull, 0ull, 0ull, 0ull};
            while (wact) {                     // warp-uniform active-tap loop
                int d = __ffs(wact) - 1; wact &= wact - 1;
                int dr = d / 3, dc = d - dr * 3;
                int nbr = -1;
                if (pw >= 0) {
                    int r = 2 * pi + dr - 1;
                    int c = 2 * pj + dc - 1;
                    if ((unsigned)r < (unsigned)sp && (unsigned)c < (unsigned)sp)
                        nbr = Ip[r * sp + c];          // L1 hit (just read)
                }
                bool v = nbr >= 0;
                const float* ap = Fp + (size_t)max(nbr, 0) * 32;
                const float* wd = sW + d * 1024 + chb;
                #pragma unroll
                for (int q = 0; q < 8; q++) {
                    float4 xq = v ? __ldcg((const float4*)(ap + q * 4))
                                  : make_float4(0.f, 0.f, 0.f, 0.f);
                    #pragma unroll
                    for (int j2 = 0; j2 < 4; j2++) {
                        float e = (j2 == 0) ? xq.x : (j2 == 1) ? xq.y
                                : (j2 == 2) ? xq.z : xq.w;
                        unsigned long long A;
                        PACK_DUP(A, e);
                        const ulonglong2* w2 =
                            (const ulonglong2*)(wd + (q * 4 + j2) * 32);
                        ulonglong2 wa = w2[0];
                        ulonglong2 wb = w2[1];
                        FMA2(acc[0], A, wa.x, acc[0]);
                        FMA2(acc[1], A, wa.y, acc[1]);
                        FMA2(acc[2], A, wb.x, acc[2]);
                        FMA2(acc[3], A, wb.y, acc[3]);
                    }
                }
            }
            // relu (packed), pool, store 8 channels
            #pragma unroll
            for (int i2 = 0; i2 < 4; i2++) {
                float2 f = upk(acc[i2]);
                f.x = fmaxf(f.x, 0.f); f.y = fmaxf(f.y, 0.f);
                unsigned long long P;
                asm("mov.b64 %0, {%1, %2};" : "=l"(P)
                    : "r"(__float_as_uint(f.x)), "r"(__float_as_uint(f.y)));
                ADD2(pool[i2], P, pool[i2]);
                acc[i2] = P;
            }
            if (p < pend) {
                ulonglong2* dst = (ulonglong2*)(Fc + (size_t)p * 32 + chb);
                dst[0] = make_ulonglong2(acc[0], acc[1]);
                dst[1] = make_ulonglong2(acc[2], acc[3]);
            }
        }
        // pool: butterfly (offsets 16,8,4 preserve lane&3 channel groups)
        #pragma unroll
        for (int i2 = 0; i2 < 4; i2++) {
            #pragma unroll
            for (int off = 16; off >= 4; off >>= 1) {
                unsigned long long o = __shfl_xor_sync(0xffffffffu, pool[i2], off);
                ADD2(pool[i2], o, pool[i2]);
            }
        }
        if (lane < 4) {
            #pragma unroll
            for (int i2 = 0; i2 < 4; i2++) {
                float2 f = upk(pool[i2]);
                atomicAdd(&spool[chb + 2 * i2],     f.x);
                atomicAdd(&spool[chb + 2 * i2 + 1], f.y);
            }
        }
        __syncthreads();
        if (tid < 32) atomicAdd(&g_pools[L * 32 + tid], spool[tid]);
        __syncthreads();
    }

    // ================= tail: 8 blocks, mini grid barriers ======================
    if (bid >= 8) { garrive(8); return; }
    gwait(8, nb_);

    int wid = tid >> 5;
    for (int k = 8; k < NLEV; k++) {
        int n = min(g_cnt[k], CAP);
        int sp = c_LS[k - 1];
        const int* Ip = g_idx + c_IOFS[k - 1];
        const float* FpT = (k & 1) ? g_FA : g_FB;
        float* FcT = (k & 1) ? g_FB : g_FA;
        const float* W = ws + (size_t)(k - 1) * 9216;
        if (tid < 32) spool[tid] = 0.f;
        __syncthreads();
        float pl = 0.f;
        for (int p = bid * 8 + wid; p < n; p += 64) {
            int pw = g_pos[k * CAP + p];
            int pi = pw >> 16, pj = pw & 0xffff;
            float acc = 0.f;
            for (int d = 0; d < 9; d++) {
                int r = 2 * pi + d / 3 - 1;
                int cc = 2 * pj + d % 3 - 1;
                if ((unsigned)r < (unsigned)sp && (unsigned)cc < (unsigned)sp) {
                    int nbv = Ip[r * sp + cc];
                    if (nbv >= 0) {
                        float row = __ldcg(&FpT[(size_t)nbv * 32 + lane]);
                        const float* wd = W + d * 1024;
                        #pragma unroll
                        for (int ci = 0; ci < 32; ci++)
                            acc = fmaf(__shfl_sync(0xffffffffu, row, ci),
                                       wd[ci * 32 + lane], acc);
                    }
                }
            }
            acc = fmaxf(acc, 0.f);
            FcT[(size_t)p * 32 + lane] = acc;
            pl += acc;
        }
        atomicAdd(&spool[lane], pl);
        __syncthreads();
        if (tid < 32) atomicAdd(&g_pools[k * 32 + tid], spool[tid]);
        gwait(9 + (k - 8), 8);
    }

    if (bid != 0) return;

    // MLP: feat[448] -> 256 relu -> 128 (reuse sW as sf/sh); block 0 only
    float* sf = sW;
    float* sh = sW + 448;
    for (int i = tid; i < 448; i += 256) {
        int k = i >> 5;
        float cnt = (float)max(g_cnt[k], 1);
        sf[i] = g_pools[i] / cnt;
    }
    __syncthreads();
    {
        float acc = bm1[tid];
        #pragma unroll 4
        for (int i = 0; i < 448; i++) acc = fmaf(sf[i], wm1[i * 256 + tid], acc);
        sh[tid] = fmaxf(acc, 0.f);
    }
    __syncthreads();
    if (tid < 128) {
        float acc = bm2[tid];
        #pragma unroll 4
        for (int j = 0; j < 256; j++) acc = fmaf(sh[j], wm2[j * 128 + tid], acc);
        out[tid] = acc;
    }

    // re-zero state for next replay (bars + scnt reset by next build_all0)
    __syncthreads();
    for (int i = tid; i < NLEV * 32; i += 256) g_pools[i] = 0.f;
    if (tid < NLEV) g_cnt[tid] = 0;
}

// ---- host launch ---------------------------------------------------------------
extern "C" void kernel_launch(void* const* d_in, const int* in_sizes, int n_in,
                              void* d_out, int out_size) {
    const float* x    = (const float*)d_in[0];
    const float* mask = (const float*)d_in[1];
    const float* w1   = (const float*)d_in[2];
    const float* ws   = (const float*)d_in[3];
    const float* wm1  = (const float*)d_in[4];
    const float* bm1  = (const float*)d_in[5];
    const float* wm2  = (const float*)d_in[6];
    const float* bm2  = (const float*)d_in[7];
    float* out = (float*)d_out;

    build_all0<<<256, 1024>>>(mask);

    int occ = 0, sms = 0;
    cudaOccupancyMaxActiveBlocksPerMultiprocessor(&occ, main_kernel, 256, 0);
    cudaDeviceGetAttribute(&sms, cudaDevAttrMultiProcessorCount, 0);
    int grid = occ * sms;
    if (grid > 592) grid = 592;
    if (grid < 8) grid = 8;

    main_kernel<<<grid, 256>>>(x, w1, ws, wm1, bm1, wm2, bm2, out);
}

// round 17
// speedup vs baseline: 1.1240x; 1.1240x over previous
#include <cuda_runtime.h>
#include <cuda_pipeline.h>
#include <cstdint>
#include <cstring>

// ============================================================================
// Sparse masked CNN pyramid (14 levels) + MLP head — round 17.
// = R14 (best, 283.1us: depth-3 cp.async tap pipeline) + two isolated fixes:
//   (a) per-level first-tile neighbor indices loaded BEFORE the grid barrier
//       (index maps are pre-kernel data), and next-tile indices prefetched
//       right after priming the current tile (overlap idx latency with FMAs)
//   (b) idle blocks skip weight staging + level body (L5..L7)
// ============================================================================

#define CAP 131072
#define NLEV 14
#define IDX_TOTAL 5592407

__device__ __align__(16) float g_FA[CAP * 32];
__device__ __align__(16) float g_FB[CAP * 32];
__device__ int   g_idx[IDX_TOTAL];
__device__ int   g_pos[NLEV * CAP];
__device__ int   g_cnt[NLEV];              // zero-init; block0 re-zeroes at end
__device__ float g_pools[NLEV * 32];       // zero-init; block0 re-zeroes at end
__device__ volatile unsigned g_bars[16];   // zeroed by build_all0 each replay

__constant__ int c_LS[NLEV]   = {2048,1024,512,256,128,64,32,16,8,4,2,1,1,1};
__constant__ int c_IOFS[NLEV] = {0,4194304,5242880,5505024,5570560,5586944,5591040,
                                 5592064,5592320,5592384,5592400,5592404,5592405,5592406};

// dynamic smem (floats): sW[9216] | sA[8 warps][3 bufs][8 pos][36] | spool[32] | sball[2]
#define SA_OFF   9216
#define SA_WARP  (3 * 288)
#define SPOOL_OFF (SA_OFF + 8 * SA_WARP)
#define SBALL_OFF (SPOOL_OFF + 32)
#define SMEM_MAIN ((SBALL_OFF + 8) * 4)

#define FMA2(d, a, b, c) \
    asm("fma.rn.f32x2 %0, %1, %2, %3;" : "=l"(d) : "l"(a), "l"(b), "l"(c))
#define ADD2(d, a, b) \
    asm("add.rn.f32x2 %0, %1, %2;" : "=l"(d) : "l"(a), "l"(b))
#define PACK_DUP(d, a) \
    do { unsigned _u = __float_as_uint(a); \
         asm("mov.b64 %0, {%1, %1};" : "=l"(d) : "r"(_u)); } while (0)

__device__ __forceinline__ float2 upk(unsigned long long a) {
    float2 f; memcpy(&f, &a, 8); return f;
}

// ---- grid-wide barriers (per-epoch counters, reset by next build_all0) -------
__device__ __forceinline__ void gwait(int e, unsigned nb) {
    __syncthreads();
    if (threadIdx.x == 0) {
        __threadfence();
        atomicAdd((unsigned*)&g_bars[e], 1u);
        while (g_bars[e] < nb) __nanosleep(128);
        __threadfence();
    }
    __syncthreads();
}
__device__ __forceinline__ void garrive(int e) {
    __syncthreads();
    __threadfence();
    if (threadIdx.x == 0) atomicAdd((unsigned*)&g_bars[e], 1u);
}

// ---- block compaction step (1024-thread blocks only) -------------------------
__device__ __forceinline__ void emit(int level, bool act, int lin, int posword,
                                     int iofs, unsigned* bitdst) {
    __shared__ int ewcnt[32];
    __shared__ int ewbase[32];
    __shared__ int ebbase;
    int tid = threadIdx.x, wid = tid >> 5, lane = tid & 31;
    unsigned m = __ballot_sync(0xffffffffu, act);
    if (lane == 0) {
        ewcnt[wid] = __popc(m);
        if (bitdst) bitdst[wid] = m;
    }
    __syncthreads();
    if (tid < 32) {
        int cc = ewcnt[tid];
        int x = cc;
        #pragma unroll
        for (int o = 1; o < 32; o <<= 1) {
            int y = __shfl_up_sync(0xffffffffu, x, o);
            if (tid >= o) x += y;
        }
        ewbase[tid] = x - cc;
        if (tid == 31) ebbase = atomicAdd(&g_cnt[level], x);
    }
    __syncthreads();
    int idx = -1;
    if (act) {
        idx = ebbase + ewbase[wid] + __popc(m & ((1u << lane) - 1u));
        if (idx < CAP) g_pos[level * CAP + idx] = posword;
        else idx = -1;
    }
    if (lin >= 0) g_idx[iofs + lin] = idx;
    __syncthreads();
}

__device__ __forceinline__ int getbit(const unsigned* a, int c) {
    return (a[c >> 5] >> (c & 31)) & 1;
}

// ---- build: levels 0..7; zero barrier counters --------------------------------
__global__ __launch_bounds__(1024) void build_all0(const float* __restrict__ mask) {
    if (blockIdx.x == 0 && threadIdx.x < 16) g_bars[threadIdx.x] = 0;

    __shared__ unsigned a0[512];
    __shared__ unsigned a1[128];
    __shared__ unsigned a2[32];
    __shared__ unsigned a3[8];
    __shared__ unsigned a4[32];
    __shared__ unsigned a5[32];
    __shared__ unsigned a6[32];
    int tid = threadIdx.x;
    int tx = blockIdx.x & 15, ty = blockIdx.x >> 4;

    for (int r = 0; r < 16; r++) {
        int c = r * 1024 + tid;
        int li = c >> 7, lj = c & 127;
        int i = ty * 128 + li, j = tx * 128 + lj;
        bool act = (mask[i * 2048 + j] != 0.0f);
        emit(0, act, i * 2048 + j, (i << 16) | j, c_IOFS[0], a0 + r * 32);
    }
    unsigned* bits[8] = {a0, a1, a2, a3, a4, a5, a6, nullptr};
    #pragma unroll
    for (int L = 1; L <= 7; L++) {
        int t = 128 >> L;
        int cells = t * t;
        int chunks = (cells + 1023) >> 10;
        int tprev = t * 2;
        for (int r = 0; r < chunks; r++) {
            int c = r * 1024 + tid;
            bool act = false;
            int lin = -1, pw = 0;
            if (c < cells) {
                int li = c / t, lj = c - li * t;
                int c00 = (2 * li) * tprev + 2 * lj;
                const unsigned* pb = bits[L - 1];
                act = getbit(pb, c00) | getbit(pb, c00 + 1) |
                      getbit(pb, c00 + tprev) | getbit(pb, c00 + tprev + 1);
                int i = ty * t + li, j = tx * t + lj;
                lin = i * (2048 >> L) + j;
                pw = (i << 16) | j;
            }
            emit(L, act, lin, pw, c_IOFS[L], (L < 7) ? (bits[L] + r * 32) : nullptr);
        }
    }
}

// ---- neighbor-index fetch for one position ------------------------------------
__device__ __forceinline__ void fetch_nbrs(int pw, const int* __restrict__ Ip,
                                           int sp, int nb[9]) {
    int pi = pw >> 16, pj = pw & 0xffff;
    #pragma unroll
    for (int d = 0; d < 9; d++) {
        int a = -1;
        if (pw >= 0) {
            int r = 2 * pi + d / 3 - 1;
            int c = 2 * pj + d % 3 - 1;
            if ((unsigned)r < (unsigned)sp && (unsigned)c < (unsigned)sp)
                a = Ip[r * sp + c];
        }
        nb[d] = a;
    }
}

// ---- persistent main kernel ---------------------------------------------------
__global__ __launch_bounds__(256) void main_kernel(
    const float* __restrict__ x,  const float* __restrict__ w1,
    const float* __restrict__ ws,
    const float* __restrict__ wm1, const float* __restrict__ bm1,
    const float* __restrict__ wm2, const float* __restrict__ bm2,
    float* __restrict__ out) {
    extern __shared__ __align__(16) float smem[];
    float* sW = smem;
    float* sA = smem + SA_OFF;
    float* spool = smem + SPOOL_OFF;
    unsigned* sball = (unsigned*)(smem + SBALL_OFF);

    int tid = threadIdx.x, bid = blockIdx.x;
    int lane = tid & 31;
    unsigned nb_ = gridDim.x;

    // ================= phase 0: conv1 (all blocks) + build_top (last block) ===
    for (int t = tid; t < 800; t += 256) sW[t] = w1[t];
    if (tid < 32) spool[tid] = 0.f;
    __syncthreads();
    {
        int n = min(g_cnt[0], CAP);
        int gw = (bid * 256 + tid) >> 5;
        int nw = (int)nb_ * 8;
        float pl = 0.f;
        for (int p = gw; p < n; p += nw) {
            int pw = g_pos[p];
            int i = pw >> 16, j = pw & 0xffff;
            float acc = 0.f;
            #pragma unroll
            for (int dy = 0; dy < 5; dy++) {
                int r = i + dy - 2;
                bool rv = (unsigned)r < 2048u;
                #pragma unroll
                for (int dx = 0; dx < 5; dx++) {
                    int cc = j + dx - 2;
                    float xv = (rv && (unsigned)cc < 2048u) ? x[r * 2048 + cc] : 0.f;
                    acc = fmaf(xv, sW[(dy * 5 + dx) * 32 + lane], acc);
                }
            }
            acc = fmaxf(acc, 0.f);
            g_FA[(size_t)p * 32 + lane] = acc;
            pl += acc;
        }
        atomicAdd(&spool[lane], pl);
    }
    if (bid == nb_ - 1) {
        for (int k = 8; k < NLEV; k++) {
            int s = c_LS[k], sp = c_LS[k - 1];
            int cells = s * s;
            const int* Ip = g_idx + c_IOFS[k - 1];
            bool act = false;
            int pwv = 0;
            if (tid < cells) {
                int i = tid / s, j = tid - i * s;
                #pragma unroll
                for (int di = 0; di < 2; di++)
                    #pragma unroll
                    for (int dj = 0; dj < 2; dj++) {
                        int r = 2 * i + di, cc = 2 * j + dj;
                        if (r < sp && cc < sp && __ldcg(&Ip[r * sp + cc]) >= 0)
                            act = true;
                    }
                pwv = (i << 16) | j;
            }
            unsigned m = __ballot_sync(0xffffffffu, act);
            if (tid == 0)  sball[0] = m;
            if (tid == 32) sball[1] = m;
            __syncthreads();
            int cnt0 = __popc(sball[0]);
            int total = cnt0 + (cells > 32 ? __popc(sball[1]) : 0);
            if (tid == 0) g_cnt[k] = total;
            if (tid < cells) {
                int idx = -1;
                if (act) {
                    idx = (tid < 32 ? 0 : cnt0) + __popc(m & ((1u << (tid & 31)) - 1u));
                    g_pos[k * CAP + idx] = pwv;
                }
                g_idx[c_IOFS[k] + tid] = idx;
            }
            __syncthreads();
        }
    }
    __syncthreads();
    if (tid < 32) atomicAdd(&g_pools[tid], spool[tid]);
    __syncthreads();

    // ================= levels 1..7: depth-3 cp.async pipelined sparse conv =====
    int pid  = tid >> 2;           // 0..63 position within 64-pos step
    int chb  = (tid & 3) * 8;      // 8 output channels
    int w    = tid >> 5;           // warp id 0..7
    int srow = (lane >> 2);        // staging row (0..7) for this lane's quad
    int cch  = lane & 3;           // staging chunk (0..3) this lane copies
    float* sAw = sA + w * SA_WARP; // this warp's 3 staging buffers

    #pragma unroll 1
    for (int L = 1; L <= 7; L++) {
        // level geometry from pre-kernel data (safe before the barrier)
        const float* __restrict__ Fp = (L & 1) ? g_FA : g_FB;
        float* __restrict__ Fc = (L & 1) ? g_FB : g_FA;
        int sp = c_LS[L - 1];
        const int* __restrict__ Ip = g_idx + c_IOFS[L - 1];
        const int* __restrict__ posl = g_pos + L * CAP;
        int n = min(g_cnt[L], CAP);

        int chunk = (n + (int)nb_ - 1) / (int)nb_;
        int start = bid * chunk;
        int pend  = min(start + chunk, n);
        bool active = (start < pend);

        // (a) first tile's neighbor indices, loaded BEFORE the barrier
        int nbc[9];
        int pwc = -1;
        if (active) {
            int p = start + pid;
            pwc = (p < pend) ? posl[p] : -1;
            fetch_nbrs(pwc, Ip, sp, nbc);
        }
        // (b) idle blocks skip weight staging
        if (active) {
            const float4* src = (const float4*)(ws + (size_t)(L - 1) * 9216);
            float4* dst = (float4*)sW;
            #pragma unroll
            for (int t = 0; t < 9; t++) dst[tid + t * 256] = src[tid + t * 256];
        }
        if (tid < 32) spool[tid] = 0.f;
        gwait(L - 1, nb_);

        if (active) {
            unsigned long long pool[4] = {0ull, 0ull, 0ull, 0ull};
            for (int base = start; base < pend; base += 64) {
                int p = base + pid;

                // prime taps 0,1,2 into buffers 0,1,2 (indices already in nbc)
                #pragma unroll
                for (int d0 = 0; d0 < 3; d0++) {
                    int nn = nbc[d0];
                    const float* src = Fp + (size_t)max(nn, 0) * 32 + cch * 4;
                    float* dst = sAw + d0 * 288 + srow * 36 + cch * 4;
                    size_t z = (nn >= 0) ? 0 : 16;
                    __pipeline_memcpy_async(dst, src, 16, z);
                    __pipeline_memcpy_async(dst + 16, src + 16, 16, z);
                    __pipeline_commit();
                }

                // prefetch NEXT tile's indices (overlaps with tap FMAs below)
                int nbn[9];
                int pwn = -1;
                {
                    int pn = base + 64 + pid;
                    pwn = (pn < pend) ? posl[pn] : -1;
                    fetch_nbrs(pwn, Ip, sp, nbn);
                }

                unsigned long long acc[4] = {0ull, 0ull, 0ull, 0ull};
                #pragma unroll
                for (int d = 0; d < 9; d++) {
                    if (d <= 6)      __pipeline_wait_prior(2);
                    else if (d == 7) __pipeline_wait_prior(1);
                    else             __pipeline_wait_prior(0);
                    __syncwarp();
                    if (__ballot_sync(0xffffffffu, nbc[d] >= 0)) {
                        const float* row = sAw + (d % 3) * 288 + srow * 36;
                        const float* wd = sW + d * 1024 + chb;
                        #pragma unroll
                        for (int q = 0; q < 8; q++) {
                            float4 xq = *(const float4*)(row + q * 4);
                            #pragma unroll
                            for (int j2 = 0; j2 < 4; j2++) {
                                float e = (j2 == 0) ? xq.x : (j2 == 1) ? xq.y
                                        : (j2 == 2) ? xq.z : xq.w;
                                unsigned long long A;
                                PACK_DUP(A, e);
                                const ulonglong2* w2 =
                                    (const ulonglong2*)(wd + (q * 4 + j2) * 32);
                                ulonglong2 wa = w2[0];
                                ulonglong2 wb = w2[1];
                                FMA2(acc[0], A, wa.x, acc[0]);
                                FMA2(acc[1], A, wa.y, acc[1]);
                                FMA2(acc[2], A, wb.x, acc[2]);
                                FMA2(acc[3], A, wb.y, acc[3]);
                            }
                        }
                    }
                    __syncwarp();          // all lanes done reading buf (d%3)
                    if (d + 3 <= 8) {      // refill it with tap d+3
                        int nn = nbc[d + 3];
                        const float* src = Fp + (size_t)max(nn, 0) * 32 + cch * 4;
                        float* dst = sAw + (d % 3) * 288 + srow * 36 + cch * 4;
                        size_t z = (nn >= 0) ? 0 : 16;
                        __pipeline_memcpy_async(dst, src, 16, z);
                        __pipeline_memcpy_async(dst + 16, src + 16, 16, z);
                        __pipeline_commit();
                    }
                }

                // relu (packed), pool, store 8 channels
                #pragma unroll
                for (int i2 = 0; i2 < 4; i2++) {
                    float2 f = upk(acc[i2]);
                    f.x = fmaxf(f.x, 0.f); f.y = fmaxf(f.y, 0.f);
                    unsigned long long P;
                    asm("mov.b64 %0, {%1, %2};" : "=l"(P)
                        : "r"(__float_as_uint(f.x)), "r"(__float_as_uint(f.y)));
                    ADD2(pool[i2], P, pool[i2]);
                    acc[i2] = P;
                }
                if (p < pend) {
                    ulonglong2* dst = (ulonglong2*)(Fc + (size_t)p * 32 + chb);
                    dst[0] = make_ulonglong2(acc[0], acc[1]);
                    dst[1] = make_ulonglong2(acc[2], acc[3]);
                }

                // rotate prefetched indices into place
                pwc = pwn;
                #pragma unroll
                for (int d = 0; d < 9; d++) nbc[d] = nbn[d];
            }
            // pool: butterfly (offsets 16,8,4 preserve lane&3 channel groups)
            #pragma unroll
            for (int i2 = 0; i2 < 4; i2++) {
                #pragma unroll
                for (int off = 16; off >= 4; off >>= 1) {
                    unsigned long long o = __shfl_xor_sync(0xffffffffu, pool[i2], off);
                    ADD2(pool[i2], o, pool[i2]);
                }
            }
            if (lane < 4) {
                #pragma unroll
                for (int i2 = 0; i2 < 4; i2++) {
                    float2 f = upk(pool[i2]);
                    atomicAdd(&spool[chb + 2 * i2],     f.x);
                    atomicAdd(&spool[chb + 2 * i2 + 1], f.y);
                }
            }
        }
        __syncthreads();
        if (active && tid < 32) atomicAdd(&g_pools[L * 32 + tid], spool[tid]);
        __syncthreads();
    }

    // ================= tail: 8 blocks, mini grid barriers ======================
    if (bid >= 8) { garrive(7); return; }
    gwait(7, nb_);

    int wid = tid >> 5;
    for (int k = 8; k < NLEV; k++) {
        int n = min(g_cnt[k], CAP);
        int sp = c_LS[k - 1];
        const int* Ip = g_idx + c_IOFS[k - 1];
        const float* FpT = (k & 1) ? g_FA : g_FB;
        float* FcT = (k & 1) ? g_FB : g_FA;
        const float* W = ws + (size_t)(k - 1) * 9216;
        if (tid < 32) spool[tid] = 0.f;
        __syncthreads();
        float pl = 0.f;
        for (int p = bid * 8 + wid; p < n; p += 64) {
            int pw = g_pos[k * CAP + p];
            int pi = pw >> 16, pj = pw & 0xffff;
            float acc = 0.f;
            for (int d = 0; d < 9; d++) {
                int r = 2 * pi + d / 3 - 1;
                int cc = 2 * pj + d % 3 - 1;
                if ((unsigned)r < (unsigned)sp && (unsigned)cc < (unsigned)sp) {
                    int nbv = Ip[r * sp + cc];
                    if (nbv >= 0) {
                        float row = __ldcg(&FpT[(size_t)nbv * 32 + lane]);
                        const float* wd = W + d * 1024;
                        #pragma unroll
                        for (int ci = 0; ci < 32; ci++)
                            acc = fmaf(__shfl_sync(0xffffffffu, row, ci),
                                       wd[ci * 32 + lane], acc);
                    }
                }
            }
            acc = fmaxf(acc, 0.f);
            FcT[(size_t)p * 32 + lane] = acc;
            pl += acc;
        }
        atomicAdd(&spool[lane], pl);
        __syncthreads();
        if (tid < 32) atomicAdd(&g_pools[k * 32 + tid], spool[tid]);
        gwait(8 + (k - 8), 8);
    }

    if (bid != 0) return;

    // MLP: feat[448] -> 256 relu -> 128 (reuse sW as sf/sh); block 0 only
    float* sf = sW;
    float* sh = sW + 448;
    for (int i = tid; i < 448; i += 256) {
        int k = i >> 5;
        float cnt = (float)max(g_cnt[k], 1);
        sf[i] = g_pools[i] / cnt;
    }
    __syncthreads();
    {
        float acc = bm1[tid];
        #pragma unroll 4
        for (int i = 0; i < 448; i++) acc = fmaf(sf[i], wm1[i * 256 + tid], acc);
        sh[tid] = fmaxf(acc, 0.f);
    }
    __syncthreads();
    if (tid < 128) {
        float acc = bm2[tid];
        #pragma unroll 4
        for (int j = 0; j < 256; j++) acc = fmaf(sh[j], wm2[j * 128 + tid], acc);
        out[tid] = acc;
    }

    // re-zero state for next replay (bars reset by next build_all0)
    __syncthreads();
    for (int i = tid; i < NLEV * 32; i += 256) g_pools[i] = 0.f;
    if (tid < NLEV) g_cnt[tid] = 0;
}

// ---- host launch ---------------------------------------------------------------
extern "C" void kernel_launch(void* const* d_in, const int* in_sizes, int n_in,
                              void* d_out, int out_size) {
    const float* x    = (const float*)d_in[0];
    const float* mask = (const float*)d_in[1];
    const float* w1   = (const float*)d_in[2];
    const float* ws   = (const float*)d_in[3];
    const float* wm1  = (const float*)d_in[4];
    const float* bm1  = (const float*)d_in[5];
    const float* wm2  = (const float*)d_in[6];
    const float* bm2  = (const float*)d_in[7];
    float* out = (float*)d_out;

    cudaFuncSetAttribute((const void*)main_kernel,
                         cudaFuncAttributeMaxDynamicSharedMemorySize, SMEM_MAIN);

    build_all0<<<256, 1024>>>(mask);

    int occ = 0, sms = 0;
    cudaOccupancyMaxActiveBlocksPerMultiprocessor(&occ, main_kernel, 256, SMEM_MAIN);
    cudaDeviceGetAttribute(&sms, cudaDevAttrMultiProcessorCount, 0);
    int grid = occ * sms;
    if (grid > 592) grid = 592;
    if (grid < 8) grid = 8;

    main_kernel<<<grid, 256, SMEM_MAIN>>>(x, w1, ws, wm1, bm1, wm2, bm2, out);
}